// round 16
// baseline (speedup 1.0000x reference)
#include <cuda_runtime.h>
#include <cstdint>

#define LROW 2048
#define HALF 1024         // outputs per CTA (row split in 2)
#define HID  128
#define TPB  128          // 4 warps
#define NPASS 16          // 16 passes x 64 outputs = 1024 per CTA
#define PCH  4            // passes per chunk
#define XS_LEN 1040       // 4 halo + 1024 + 4 halo + pad
#define W1S 136           // padded row stride (136 % 32 == 8 -> conflict-free)

typedef unsigned long long u64;

#define PACK_F32X2(o, lo, hi) \
    asm("mov.b64 %0, {%1, %2};" : "=l"(o) : "f"(lo), "f"(hi))
#define UNPACK_F32X2(lo, hi, i) \
    asm("mov.b64 {%0, %1}, %2;" : "=f"(lo), "=f"(hi) : "l"(i))
#define FMA_F32X2(d, a, b, c) \
    asm("fma.rn.f32x2 %0, %1, %2, %3;" : "=l"(d) : "l"(a), "l"(b), "l"(c))
#define ABS2_F32X2(d, a) \
    asm("and.b64 %0, %1, 0x7FFFFFFF7FFFFFFF;" : "=l"(d) : "l"(a))

__device__ __forceinline__ uint32_t to_tf32(float v) {
    uint32_t r;
    asm("cvt.rna.tf32.f32 %0, %1;" : "=r"(r) : "f"(v));
    return r;
}

__device__ __forceinline__ void mma_tf32(
    float& d0, float& d1, float& d2, float& d3,
    uint32_t a0, uint32_t a1, uint32_t a2, uint32_t a3,
    uint32_t b0, uint32_t b1,
    float c0, float c1, float c2, float c3)
{
    asm("mma.sync.aligned.m16n8k8.row.col.f32.tf32.tf32.f32 "
        "{%0,%1,%2,%3}, {%4,%5,%6,%7}, {%8,%9}, {%10,%11,%12,%13};"
        : "=f"(d0), "=f"(d1), "=f"(d2), "=f"(d3)
        : "r"(a0), "r"(a1), "r"(a2), "r"(a3),
          "r"(b0), "r"(b1),
          "f"(c0), "f"(c1), "f"(c2), "f"(c3));
}

__global__ __launch_bounds__(TPB, 6)   // 85-reg cap -> 6 CTAs/SM
void simconv1d_mma(const float* __restrict__ x,
                   const float* __restrict__ W1,
                   const float* __restrict__ b1,
                   const float* __restrict__ W2,
                   const float* __restrict__ b2,
                   float* __restrict__ out)
{
    __shared__ __align__(16) uint32_t xs[XS_LEN];     // tf32 padded half-row
    __shared__ __align__(16) uint32_t w1s[8 * W1S];   // tf32, K-rows 0..7 only
    __shared__ __align__(8)  float b1s[HID];
    __shared__ __align__(8)  float w8s[HID];          // W1 row 8 (fp32)
    __shared__ __align__(8)  float hw2s[HID];         // 0.5 * W2 (for abs-relu)

    const int row  = blockIdx.x >> 1;          // b*64 + h
    const int h0   = (blockIdx.x & 1) * HALF;  // output offset within row
    const int tid  = threadIdx.x;
    const float* xr = x + (size_t)row * LROW;

    // Stage padded x segment (tf32). xs[j] corresponds to x[h0 + j - 4].
    for (int i = tid; i < HALF + 8; i += TPB) {
        const int gidx = h0 + i - 4;
        uint32_t v = 0u;
        if (gidx >= 0 && gidx < LROW) v = to_tf32(xr[gidx]);
        xs[i] = v;
    }
    // Stage W1 K-rows 0..7 (tf32); cols >= 128 zero-padded.
    for (int i = tid; i < 8 * W1S; i += TPB) {
        int r = i / W1S, c = i % W1S;
        w1s[i] = (c < HID) ? to_tf32(W1[r * HID + c]) : 0u;
    }
    if (tid < HID) {
        b1s[tid]  = b1[tid];
        w8s[tid]  = W1[8 * HID + tid];    // tap-8 row, full fp32
        hw2s[tid] = 0.5f * W2[tid];       // relu(d)*w2 = hw2*d + hw2*|d|
    }
    __syncthreads();

    const int lane = tid & 31;
    const int warp = tid >> 5;
    const int g = lane >> 2;      // groupID (row within fragment)
    const int t = lane & 3;       // threadID_in_group
    const float b2v = b2[0];
    float* orow = out + (size_t)row * LROW + h0;

    #pragma unroll 1
    for (int pc = 0; pc < NPASS / PCH; pc++) {
        uint32_t A[PCH][4];
        u64 x8da[PCH], x8db[PCH];     // tap-8 x, duplicated (x,x) for FFMA2
        u64 y0p[PCH], y1p[PCH];       // packed accumulators (rows g, g+8)
        #pragma unroll
        for (int q = 0; q < PCH; q++) {
            const int o0 = (pc * PCH + q) * 64 + warp * 16;   // local offset
            const int base = o0 + g + t;
            // Toeplitz A (K=8): a0=A[g][t], a1=A[g+8][t], a2=A[g][t+4], a3=A[g+8][t+4]
            A[q][0] = xs[base];
            A[q][1] = xs[base + 8];
            A[q][2] = xs[base + 4];
            A[q][3] = xs[base + 12];
            // tap-8 inputs, pre-duplicated once per chunk.
            const float x8a = __uint_as_float(xs[o0 + g + 8]);
            const float x8b = __uint_as_float(xs[o0 + g + 16]);
            PACK_F32X2(x8da[q], x8a, x8a);
            PACK_F32X2(x8db[q], x8b, x8b);
            y0p[q] = 0ull;
            y1p[q] = 0ull;
        }

        #pragma unroll 2
        for (int n = 0; n < 16; n++) {
            const int nc = n * 8;
            // B fragments (col-major 8x8): b0 = W[t][nc+g], b1 = W[t+4][nc+g]
            const uint32_t bk0 = w1s[t * W1S + nc + g];
            const uint32_t bk1 = w1s[(t + 4) * W1S + nc + g];

            const u64 biasq = *(const u64*)&b1s[nc + 2 * t];
            const u64 w8q   = *(const u64*)&w8s[nc + 2 * t];
            const u64 hw2q  = *(const u64*)&hw2s[nc + 2 * t];

            #pragma unroll
            for (int q = 0; q < PCH; q++) {
                // Packed tap-8 fold: c = x8*w8 + b1 for d-pair (2 FFMA2).
                u64 c01, c23;
                FMA_F32X2(c01, x8da[q], w8q, biasq);
                FMA_F32X2(c23, x8db[q], w8q, biasq);
                float c0, c1, c2, c3;
                UNPACK_F32X2(c0, c1, c01);   // register aliasing — free
                UNPACK_F32X2(c2, c3, c23);

                float d0, d1, d2, d3;
                mma_tf32(d0, d1, d2, d3,
                         A[q][0], A[q][1], A[q][2], A[q][3],
                         bk0, bk1,
                         c0, c1, c2, c3);

                // Packed relu+proj: relu(d)*w2 = hw2*d + hw2*|d| (exact).
                u64 p01, p23, a01, a23;
                PACK_F32X2(p01, d0, d1);
                PACK_F32X2(p23, d2, d3);
                ABS2_F32X2(a01, p01);        // one LOP handles 2 values
                ABS2_F32X2(a23, p23);
                FMA_F32X2(y0p[q], p01, hw2q, y0p[q]);
                FMA_F32X2(y0p[q], a01, hw2q, y0p[q]);
                FMA_F32X2(y1p[q], p23, hw2q, y1p[q]);
                FMA_F32X2(y1p[q], a23, hw2q, y1p[q]);
            }
        }

        #pragma unroll
        for (int q = 0; q < PCH; q++) {
            float y0lo, y0hi, y1lo, y1hi;
            UNPACK_F32X2(y0lo, y0hi, y0p[q]);
            UNPACK_F32X2(y1lo, y1hi, y1p[q]);
            float y0 = y0lo + y0hi;
            float y1 = y1lo + y1hi;
            y0 += __shfl_xor_sync(0xffffffffu, y0, 1);
            y0 += __shfl_xor_sync(0xffffffffu, y0, 2);
            y1 += __shfl_xor_sync(0xffffffffu, y1, 1);
            y1 += __shfl_xor_sync(0xffffffffu, y1, 2);
            if (t == 0) {
                const int o0 = (pc * PCH + q) * 64 + warp * 16;
                orow[o0 + g]     = y0 + b2v;
                orow[o0 + g + 8] = y1 + b2v;
            }
        }
    }
}

extern "C" void kernel_launch(void* const* d_in, const int* in_sizes, int n_in,
                              void* d_out, int out_size)
{
    const float* x  = (const float*)d_in[0];  // (8, 64, 2048)
    const float* W1 = (const float*)d_in[1];  // (9, 128)
    const float* b1 = (const float*)d_in[2];  // (128,)
    const float* W2 = (const float*)d_in[3];  // (128, 1)
    const float* b2 = (const float*)d_in[4];  // (1,)
    float* out = (float*)d_out;               // (8, 64, 2048)

    simconv1d_mma<<<8 * 64 * 2, TPB>>>(x, W1, b1, W2, b2, out);
}

// round 17
// speedup vs baseline: 1.1719x; 1.1719x over previous
#include <cuda_runtime.h>
#include <cstdint>

#define LROW 2048
#define HALF 1024         // outputs per CTA (row split in 2)
#define HID  128
#define TPB  128          // 4 warps
#define NPASS 16          // 16 passes x 64 outputs = 1024 per CTA
#define PCH  4            // passes per chunk
#define XS_LEN 1040       // 4 halo + 1024 + 4 halo + pad
#define W1S 136           // padded row stride (136 % 32 == 8 -> conflict-free)

typedef unsigned long long u64;

#define PACK_F32X2(o, lo, hi) \
    asm("mov.b64 %0, {%1, %2};" : "=l"(o) : "f"(lo), "f"(hi))
#define UNPACK_F32X2(lo, hi, i) \
    asm("mov.b64 {%0, %1}, %2;" : "=f"(lo), "=f"(hi) : "l"(i))
#define FMA_F32X2(d, a, b, c) \
    asm("fma.rn.f32x2 %0, %1, %2, %3;" : "=l"(d) : "l"(a), "l"(b), "l"(c))

__device__ __forceinline__ uint32_t to_tf32(float v) {
    uint32_t r;
    asm("cvt.rna.tf32.f32 %0, %1;" : "=r"(r) : "f"(v));
    return r;
}

__device__ __forceinline__ void mma_tf32(
    float& d0, float& d1, float& d2, float& d3,
    uint32_t a0, uint32_t a1, uint32_t a2, uint32_t a3,
    uint32_t b0, uint32_t b1,
    float c0, float c1, float c2, float c3)
{
    asm("mma.sync.aligned.m16n8k8.row.col.f32.tf32.tf32.f32 "
        "{%0,%1,%2,%3}, {%4,%5,%6,%7}, {%8,%9}, {%10,%11,%12,%13};"
        : "=f"(d0), "=f"(d1), "=f"(d2), "=f"(d3)
        : "r"(a0), "r"(a1), "r"(a2), "r"(a3),
          "r"(b0), "r"(b1),
          "f"(c0), "f"(c1), "f"(c2), "f"(c3));
}

__global__ __launch_bounds__(TPB, 5)   // 102-reg cap: room for dual accumulators
void simconv1d_mma(const float* __restrict__ x,
                   const float* __restrict__ W1,
                   const float* __restrict__ b1,
                   const float* __restrict__ W2,
                   const float* __restrict__ b2,
                   float* __restrict__ out)
{
    __shared__ __align__(16) uint32_t xs[XS_LEN];     // tf32 padded half-row
    __shared__ __align__(16) uint32_t w1s[8 * W1S];   // tf32, K-rows 0..7 only
    __shared__ __align__(8)  float b1s[HID];
    __shared__ __align__(8)  float w8s[HID];          // W1 row 8 (fp32)
    __shared__ __align__(8)  float w2s[HID];

    const int row  = blockIdx.x >> 1;          // b*64 + h
    const int h0   = (blockIdx.x & 1) * HALF;  // output offset within row
    const int tid  = threadIdx.x;
    const float* xr = x + (size_t)row * LROW;

    // Stage padded x segment (tf32). xs[j] corresponds to x[h0 + j - 4].
    for (int i = tid; i < HALF + 8; i += TPB) {
        const int gidx = h0 + i - 4;
        uint32_t v = 0u;
        if (gidx >= 0 && gidx < LROW) v = to_tf32(xr[gidx]);
        xs[i] = v;
    }
    // Stage W1 K-rows 0..7 (tf32); cols >= 128 zero-padded.
    for (int i = tid; i < 8 * W1S; i += TPB) {
        int r = i / W1S, c = i % W1S;
        w1s[i] = (c < HID) ? to_tf32(W1[r * HID + c]) : 0u;
    }
    if (tid < HID) {
        b1s[tid] = b1[tid];
        w8s[tid] = W1[8 * HID + tid];   // tap-8 row, full fp32
        w2s[tid] = W2[tid];
    }
    __syncthreads();

    const int lane = tid & 31;
    const int warp = tid >> 5;
    const int g = lane >> 2;      // groupID (row within fragment)
    const int t = lane & 3;       // threadID_in_group
    const float b2v = b2[0];
    float* orow = out + (size_t)row * LROW + h0;

    #pragma unroll 1
    for (int pc = 0; pc < NPASS / PCH; pc++) {
        uint32_t A[PCH][4];
        u64 x8da[PCH], x8db[PCH];       // tap-8 x, duplicated (x,x) for FFMA2
        float yA0[PCH], yA1[PCH];       // dual accumulators: half-length chains
        float yB0[PCH], yB1[PCH];
        #pragma unroll
        for (int q = 0; q < PCH; q++) {
            const int o0 = (pc * PCH + q) * 64 + warp * 16;   // local offset
            const int base = o0 + g + t;
            // Toeplitz A (K=8): a0=A[g][t], a1=A[g+8][t], a2=A[g][t+4], a3=A[g+8][t+4]
            A[q][0] = xs[base];
            A[q][1] = xs[base + 8];
            A[q][2] = xs[base + 4];
            A[q][3] = xs[base + 12];
            // tap-8 inputs, pre-duplicated once per chunk.
            const float x8a = __uint_as_float(xs[o0 + g + 8]);
            const float x8b = __uint_as_float(xs[o0 + g + 16]);
            PACK_F32X2(x8da[q], x8a, x8a);
            PACK_F32X2(x8db[q], x8b, x8b);
            yA0[q] = 0.0f; yA1[q] = 0.0f;
            yB0[q] = 0.0f; yB1[q] = 0.0f;
        }

        #pragma unroll 4
        for (int n = 0; n < 16; n++) {
            const int nc = n * 8;
            // B fragments (col-major 8x8): b0 = W[t][nc+g], b1 = W[t+4][nc+g]
            const uint32_t bk0 = w1s[t * W1S + nc + g];
            const uint32_t bk1 = w1s[(t + 4) * W1S + nc + g];

            const u64 biasq = *(const u64*)&b1s[nc + 2 * t];
            const u64 w8q   = *(const u64*)&w8s[nc + 2 * t];
            const float2 w2v = *(const float2*)&w2s[nc + 2 * t];

            #pragma unroll
            for (int q = 0; q < PCH; q++) {
                // Packed tap-8 fold: c = x8*w8 + b1 for d-pair (2 FFMA2).
                u64 c01, c23;
                FMA_F32X2(c01, x8da[q], w8q, biasq);
                FMA_F32X2(c23, x8db[q], w8q, biasq);
                float c0, c1, c2, c3;
                UNPACK_F32X2(c0, c1, c01);   // register aliasing — free
                UNPACK_F32X2(c2, c3, c23);

                float d0, d1, d2, d3;
                mma_tf32(d0, d1, d2, d3,
                         A[q][0], A[q][1], A[q][2], A[q][3],
                         bk0, bk1,
                         c0, c1, c2, c3);

                // relu + projection; independent chains per (even/odd) column.
                yA0[q] = fmaf(fmaxf(d0, 0.0f), w2v.x, yA0[q]);
                yA1[q] = fmaf(fmaxf(d1, 0.0f), w2v.y, yA1[q]);
                yB0[q] = fmaf(fmaxf(d2, 0.0f), w2v.x, yB0[q]);
                yB1[q] = fmaf(fmaxf(d3, 0.0f), w2v.y, yB1[q]);
            }
        }

        #pragma unroll
        for (int q = 0; q < PCH; q++) {
            float y0 = yA0[q] + yA1[q];
            float y1 = yB0[q] + yB1[q];
            y0 += __shfl_xor_sync(0xffffffffu, y0, 1);
            y0 += __shfl_xor_sync(0xffffffffu, y0, 2);
            y1 += __shfl_xor_sync(0xffffffffu, y1, 1);
            y1 += __shfl_xor_sync(0xffffffffu, y1, 2);
            if (t == 0) {
                const int o0 = (pc * PCH + q) * 64 + warp * 16;
                orow[o0 + g]     = y0 + b2v;
                orow[o0 + g + 8] = y1 + b2v;
            }
        }
    }
}

extern "C" void kernel_launch(void* const* d_in, const int* in_sizes, int n_in,
                              void* d_out, int out_size)
{
    const float* x  = (const float*)d_in[0];  // (8, 64, 2048)
    const float* W1 = (const float*)d_in[1];  // (9, 128)
    const float* b1 = (const float*)d_in[2];  // (128,)
    const float* W2 = (const float*)d_in[3];  // (128, 1)
    const float* b2 = (const float*)d_in[4];  // (1,)
    float* out = (float*)d_out;               // (8, 64, 2048)

    simconv1d_mma<<<8 * 64 * 2, TPB>>>(x, W1, b1, W2, b2, out);
}